// round 3
// baseline (speedup 1.0000x reference)
#include <cuda_runtime.h>
#include <math.h>

#define NT 512
#define GZ (-9.80665f)

struct SM {
    float P[441], A[441], Pn[441], T9[189], L[108];
    float H[24];        // [2][12] compact
    float HB[42];       // [2][21]  H @ B
    float HP[42];       // [2][21]  H @ Pn
    float S3[3];        // S00, S01, S11
    float r2[2];
    float Rot[9], V[3], Pp[3], Bom[3], Bac[3], Rci[9], Tci[3];
    float Rotn[9], Vn[3], Pn3[3], Om[3], vi[3];
    float in[2][9];     // t, u[6], mcov[2]
};

// skew(w)[r][c]
__device__ __forceinline__ float skf(const float* w, int r, int c) {
    if (r == 0) return (c == 0) ? 0.f : ((c == 1) ? -w[2] : w[1]);
    if (r == 1) return (c == 0) ? w[2] : ((c == 1) ? 0.f : -w[0]);
    return (c == 0) ? -w[1] : ((c == 1) ? w[0] : 0.f);
}
// (skew(w) @ R)(rr, j)
__device__ __forceinline__ float skewrowdot(const float* w, const float* R, int rr, int j) {
    if (rr == 0) return -w[2]*R[3+j] + w[1]*R[6+j];
    if (rr == 1) return  w[2]*R[0+j] - w[0]*R[6+j];
    return -w[1]*R[0+j] + w[0]*R[3+j];
}
// skew((0,0,GZ))[rr][j]
__device__ __forceinline__ float SG(int rr, int j) {
    if (rr == 0 && j == 1) return -GZ;
    if (rr == 1 && j == 0) return  GZ;
    return 0.f;
}
// (skew(g)@R)(rr,j), g=(0,0,GZ)
__device__ __forceinline__ float sgR(const float* R, int rr, int j) {
    if (rr == 0) return -GZ * R[3+j];
    if (rr == 1) return  GZ * R[0+j];
    return 0.f;
}
// polynomial SO3 coefficients (|phi| << 1 here; series exact to fp32)
__device__ __forceinline__ void so3c(float a2, float& c, float& sa, float& oc) {
    c  = 1.f + a2*(-0.5f      + a2*((1.f/24.f)  + a2*(-1.f/720.f)));
    sa = 1.f + a2*((-1.f/6.f) + a2*((1.f/120.f) + a2*(-1.f/5040.f)));
    oc = 0.5f + a2*((-1.f/24.f) + a2*(1.f/720.f));
}
__device__ __forceinline__ float j1c(float a2) {
    return (1.f/6.f) + a2*((-1.f/120.f) + a2*(1.f/5040.f));
}
// full exp(phi) into R[9]
__device__ __forceinline__ void so3exp_p(const float* phi, float* R) {
    float a2 = phi[0]*phi[0] + phi[1]*phi[1] + phi[2]*phi[2];
    float c, sa, oc; so3c(a2, c, sa, oc);
#pragma unroll
    for (int r = 0; r < 3; ++r)
#pragma unroll
        for (int q = 0; q < 3; ++q)
            R[r*3+q] = ((r == q) ? c : 0.f) + oc*phi[r]*phi[q] + sa*skf(phi, r, q);
}
__device__ __forceinline__ void mm3(const float* A, const float* B, float* C) {
#pragma unroll
    for (int p = 0; p < 3; ++p)
#pragma unroll
        for (int q = 0; q < 3; ++q)
            C[p*3+q] = A[p*3+0]*B[0*3+q] + A[p*3+1]*B[1*3+q] + A[p*3+2]*B[2*3+q];
}
__device__ __forceinline__ void normrot(float* X) {
    for (int it = 0; it < 8; ++it) {
        float Y[9], Z[9];
#pragma unroll
        for (int p = 0; p < 3; ++p)
#pragma unroll
            for (int q = 0; q < 3; ++q)
                Y[p*3+q] = X[p*3+0]*X[q*3+0] + X[p*3+1]*X[q*3+1] + X[p*3+2]*X[q*3+2];
        mm3(Y, X, Z);
#pragma unroll
        for (int m = 0; m < 9; ++m) X[m] = 1.5f*X[m] - 0.5f*Z[m];
    }
}

__global__ void __launch_bounds__(NT, 1)
iekf_kernel(const float* __restrict__ t, const float* __restrict__ u,
            const float* __restrict__ mc, const float* __restrict__ vmes,
            const float* __restrict__ ang0, float* __restrict__ out, int N)
{
    __shared__ SM s;
    const int tid = threadIdx.x;
    const bool el = (tid < 441);

    // ---------- per-thread decodes (once) ----------
    int ii = 0, jj = 0, jjT = 0, iib = 0, jl12 = 0, iib12 = 0;
    int am = 2, ar = 0, brx = 0; float asc = 0.f, aqv = 0.f;
    if (el) {
        ii = tid / 21; jj = tid - ii*21;
        jjT = jj*21 + ii; iib = ii*21; jl12 = jj*12; iib12 = ii*12;
        if (ii < 3 && jj < 3)                       { am = 0; ar = ii*3;     brx = jj*3;     asc = 0.001f; }
        else if (ii >= 3 && ii < 6 && jj >= 3 && jj < 6) { am = 0; ar = (ii-3)*3; brx = (jj-3)*3; asc = 0.01f;  }
        else if (ii == jj) {
            am = 1;
            aqv = (ii >= 9 && ii < 12) ? 6e-9f : (ii >= 12 && ii < 15) ? 2e-4f : (ii >= 15) ? 1e-9f : 0.f;
        }
    }
    const bool useT9 = el && (ii < 9);
    // H decode (threads 480..503)
    int ha = 0, hcc = 0, hbb = 0, hj = 0;
    if (tid >= 480 && tid < 504) { int k = tid - 480; ha = k/12; hcc = k - ha*12; hbb = hcc/3; hj = hcc - hbb*3; }
    // HB decode (256..297)
    int ga = 0, gc = 0;
    if (tid >= 256 && tid < 298) { int k = tid - 256; ga = k/21; gc = k - ga*21; }
    // HP decode (448..489)
    int pa = 0, pc = 0;
    if (tid >= 448 && tid < 490) { int k = tid - 448; pa = k/21; pc = k - pa*21; }
    // state lane
    const int ln = tid - 480;
    const int rp = (ln >= 0 && ln < 9) ? ln/3 : 0;
    const int rq = (ln >= 0 && ln < 9) ? ln - rp*3 : 0;

    // ---------- prologue ----------
    const float t0 = t[0];
    float tprev = t0;
    for (int k = tid; k < 441; k += NT) {
        int i = k / 21, j = k - i*21;
        float pv = 0.f;
        if (i == j) {
            if (i < 2) pv = 0.001f;
            else if (i >= 3 && i < 5) pv = 0.1f;
            else if (i >= 9 && i < 12) pv = 0.006f;
            else if (i >= 12 && i < 15) pv = 0.004f;
            else if (i >= 15 && i < 18) pv = 1e-6f;
            else if (i >= 18) pv = 0.005f;
        }
        s.P[k] = pv;
    }
    if (tid < 9) {
        float v;
        if (tid == 0) v = t[1];
        else if (tid < 7) v = u[6 + (tid-1)];
        else v = mc[2 + (tid-7)];
        s.in[1][tid] = v;
    }
    __syncthreads();
    if (tid == 0) {
        float a0 = ang0[0], a1 = ang0[1], a2 = ang0[2];
        float cr = cosf(a0), sr = sinf(a0), cp = cosf(a1), sp = sinf(a1);
        float cy = cosf(a2), sy = sinf(a2);
        float Rx[9] = {1,0,0, 0,cr,-sr, 0,sr,cr};
        float Ry[9] = {cp,0,sp, 0,1,0, -sp,0,cp};
        float Rz[9] = {cy,-sy,0, sy,cy,0, 0,0,1};
        float T[9], R0[9];
        mm3(Rz, Ry, T); mm3(T, Rx, R0);
#pragma unroll
        for (int m = 0; m < 9; ++m) { s.Rot[m] = R0[m]; s.Rci[m] = (m==0||m==4||m==8) ? 1.f : 0.f; }
        float V0[3];
#pragma unroll
        for (int q = 0; q < 3; ++q) {
            V0[q] = vmes[q];
            s.V[q] = V0[q]; s.Pp[q] = 0.f; s.Bom[q] = 0.f; s.Bac[q] = 0.f; s.Tci[q] = 0.f;
        }
        // propagate for step 1
        float dt1 = s.in[1][0] - t0;
        float w[3] = { s.in[1][1], s.in[1][2], s.in[1][3] };
        float phi[3] = { w[0]*dt1, w[1]*dt1, w[2]*dt1 };
        float E[9]; so3exp_p(phi, E);
        float Rn[9]; mm3(R0, E, Rn);
        float acc[3];
#pragma unroll
        for (int q = 0; q < 3; ++q)
            acc[q] = R0[q*3+0]*s.in[1][4] + R0[q*3+1]*s.in[1][5] + R0[q*3+2]*s.in[1][6] + ((q==2)?GZ:0.f);
        float Vn[3], Pn3[3];
#pragma unroll
        for (int q = 0; q < 3; ++q) {
            Vn[q]  = V0[q] + acc[q]*dt1;
            Pn3[q] = V0[q]*dt1 + 0.5f*acc[q]*dt1*dt1;
            s.Vn[q] = Vn[q]; s.Pn3[q] = Pn3[q]; s.Om[q] = w[q];
        }
#pragma unroll
        for (int m = 0; m < 9; ++m) s.Rotn[m] = Rn[m];
        float vi[3];
#pragma unroll
        for (int q = 0; q < 3; ++q)
            vi[q] = Rn[0*3+q]*Vn[0] + Rn[1*3+q]*Vn[1] + Rn[2*3+q]*Vn[2];
#pragma unroll
        for (int q = 0; q < 3; ++q) s.vi[q] = vi[q];
        s.r2[0] = -vi[1]; s.r2[1] = -vi[2];   // Rci=I, Tci=0
    }
    __syncthreads();

    // ---------- main loop ----------
    for (int i = 1; i < N; ++i) {
        const int cur = i & 1;
        const int nxt = cur ^ 1;
        const float tc = s.in[cur][0];
        const float dt = tc - tprev;
        tprev = tc;
        const float dt2 = dt*dt;
        const float dt3 = dt2*dt;

        // ===== PHASE 1: A, L, H, out-STG, prefetch LDG =====
        float pf = 0.f;
        if (el) {
            float gq = 0.f;
            if (am == 0) {
                float d = s.Rot[ar]*s.Rot[brx] + s.Rot[ar+1]*s.Rot[brx+1] + s.Rot[ar+2]*s.Rot[brx+2];
                gq = asc * dt2 * d;
            } else if (am == 1) gq = aqv * dt2;
            s.A[tid] = s.P[tid] + gq;
        }
        if (tid < 33) {   // outputs of step i-1
            int j = i - 1;
            if (tid < 9)       out[j*9 + tid]             = s.Rot[tid];
            else if (tid < 12) out[9*N  + j*3 + (tid-9)]  = s.V[tid-9];
            else if (tid < 15) out[12*N + j*3 + (tid-12)] = s.Pp[tid-12];
            else if (tid < 18) out[15*N + j*3 + (tid-15)] = s.Bom[tid-15];
            else if (tid < 21) out[18*N + j*3 + (tid-18)] = s.Bac[tid-18];
            else if (tid < 30) out[21*N + j*9 + (tid-21)] = s.Rci[tid-21];
            else               out[30*N + j*3 + (tid-30)] = s.Tci[tid-30];
        }
        if (tid >= 448 && tid < 457) {
            int nx = i + 1, q = tid - 448;
            if (nx < N) {
                if (q == 0) pf = t[nx];
                else if (q < 7) pf = u[nx*6 + (q-1)];
                else pf = mc[nx*2 + (q-7)];
            }
        }
        if (tid >= 448 && tid < 475) {   // L closed form, 4 entries/lane
            int base = 4*(tid - 448);
#pragma unroll
            for (int m = 0; m < 4; ++m) {
                int k = base + m;
                if (k < 108) {
                    int r = k/12, cc = k - r*12;
                    int brr = r/3, rr = r - brr*3, bc = cc/3, j = cc - bc*3;
                    float v = 0.f;
                    if (brr == 0) {
                        if (bc == 2) v = -dt * s.Rot[rr*3+j];
                    } else if (brr == 1) {
                        if (bc == 0)      v = dt * SG(rr, j);
                        else if (bc == 2) v = -dt*skewrowdot(s.V, s.Rot, rr, j) - 0.5f*dt2*sgR(s.Rot, rr, j);
                        else if (bc == 3) v = -dt * s.Rot[rr*3+j];
                    } else {
                        if (bc == 0)      v = 0.5f*dt2*SG(rr, j);
                        else if (bc == 1) v = (rr == j) ? dt : 0.f;
                        else if (bc == 2) v = -dt*skewrowdot(s.Pp, s.Rot, rr, j)
                                              - 0.5f*dt2*skewrowdot(s.V, s.Rot, rr, j)
                                              - (dt3*(1.f/6.f))*sgR(s.Rot, rr, j);
                        else              v = -0.5f*dt2*s.Rot[rr*3+j];
                    }
                    s.L[k] = v;
                }
            }
        }
        if (tid >= 480 && tid < 504) {   // H
            float hv;
            if (hbb == 0) {
                hv = s.Rotn[hj*3+0]*s.Rci[0*3+ha+1] + s.Rotn[hj*3+1]*s.Rci[1*3+ha+1] + s.Rotn[hj*3+2]*s.Rci[2*3+ha+1];
            } else if (hbb == 1) {
                hv = skf(s.Tci, ha+1, hj);
            } else if (hbb == 2) {
                hv = s.Rci[0*3+ha+1]*skf(s.vi,0,hj) + s.Rci[1*3+ha+1]*skf(s.vi,1,hj) + s.Rci[2*3+ha+1]*skf(s.vi,2,hj);
            } else {
                hv = -skf(s.Om, ha+1, hj);
            }
            s.H[ha*12+hcc] = hv;
        }
        __syncthreads();

        // ===== PHASE 2: T9, HB, prefetch STS =====
        if (tid < 189) {
            float a = s.A[tid];
#pragma unroll
            for (int cc = 0; cc < 12; ++cc) {
                const int col = (cc < 6) ? cc : cc + 3;
                a += s.L[iib12+cc] * s.A[col*21 + jj];
            }
            s.T9[tid] = a;
        }
        if (tid >= 256 && tid < 298) {
            float acc = 0.f;
#pragma unroll
            for (int l = 0; l < 12; ++l) {
                const int h = (l < 3) ? l+3 : ((l < 6) ? l+6 : l+9);
                acc += s.H[ga*12+l] * s.A[h*21 + gc];
            }
#pragma unroll
            for (int l = 0; l < 3; ++l) {
                float la = 0.f;
#pragma unroll
                for (int cc = 0; cc < 12; ++cc) {
                    const int col = (cc < 6) ? cc : cc + 3;
                    la += s.L[(3+l)*12+cc] * s.A[col*21 + gc];
                }
                acc += s.H[ga*12+l] * la;
            }
            s.HB[ga*21+gc] = acc;
        }
        if (tid >= 448 && tid < 457) s.in[nxt][tid-448] = pf;
        __syncthreads();

        // ===== PHASE 3: Pn, HP, S =====
        if (el) {
            float b = useT9 ? s.T9[tid] : s.A[tid];
            if (jj < 9) {
#pragma unroll
                for (int cc = 0; cc < 12; ++cc) {
                    const int col = (cc < 6) ? cc : cc + 3;
                    float brc = useT9 ? s.T9[iib+col] : s.A[iib+col];
                    b += brc * s.L[jl12+cc];
                }
            }
            s.Pn[tid] = b;
        }
        if (tid >= 448 && tid < 490) {
            float hp = s.HB[pa*21+pc];
            if (pc < 9) {
#pragma unroll
                for (int cc = 0; cc < 12; ++cc) {
                    const int col = (cc < 6) ? cc : cc + 3;
                    hp += s.HB[pa*21+col] * s.L[pc*12+cc];
                }
            }
            s.HP[pa*21+pc] = hp;
        }
        if (tid >= 492 && tid < 495) {
            int m = tid - 492;
            int a = (m == 2) ? 1 : 0;
            int b = (m == 0) ? 0 : 1;
            float acc = 0.f;
#pragma unroll
            for (int l = 0; l < 12; ++l) {
                const int h = (l < 3) ? l+3 : ((l < 6) ? l+6 : l+9);
                float hpv = s.HB[a*21+h];
                if (l < 3) {
#pragma unroll
                    for (int cc = 0; cc < 12; ++cc) {
                        const int col = (cc < 6) ? cc : cc + 3;
                        hpv += s.HB[a*21+col] * s.L[h*12+cc];
                    }
                }
                acc += hpv * s.H[b*12+l];
            }
            if (a == b) acc += s.in[cur][7+a];
            s.S3[m] = acc;
        }
        __syncthreads();

        // ===== PHASE 4: P update (Joseph), state update + next prop =====
        if (el) {
            const float S00 = s.S3[0], S01 = s.S3[1], S11 = s.S3[2];
            const float idet = 1.f / (S00*S11 - S01*S01);
            const float Si00 = S11*idet, Si01 = -S01*idet, Si11 = S00*idet;
            const float hp0i = s.HP[ii], hp1i = s.HP[21+ii];
            const float hp0j = s.HP[jj], hp1j = s.HP[21+jj];
            const float Ki0 = Si00*hp0i + Si01*hp1i, Ki1 = Si01*hp0i + Si11*hp1i;
            const float Kj0 = Si00*hp0j + Si01*hp1j, Kj1 = Si01*hp0j + Si11*hp1j;
            const float KSi0 = Ki0*S00 + Ki1*S01, KSi1 = Ki0*S01 + Ki1*S11;
            float v = 0.5f*(s.Pn[tid] + s.Pn[jjT])
                    - (Ki0*hp0j + Ki1*hp1j) - (Kj0*hp0i + Kj1*hp1i)
                    + (KSi0*Kj0 + KSi1*Kj1);
            s.P[tid] = v;
        }
        if (tid >= 480) {
            const float S00 = s.S3[0], S01 = s.S3[1], S11 = s.S3[2];
            const float idet = 1.f / (S00*S11 - S01*S01);
            const float Si00 = S11*idet, Si01 = -S01*idet, Si11 = S00*idet;
            const float r0 = s.r2[0], r1 = s.r2[1];
            const float w0 = Si00*r0 + Si01*r1, w1 = Si01*r0 + Si11*r1;
#define DX(c) (s.HP[(c)]*w0 + s.HP[21+(c)]*w1)
            float sv = 0.f;    // value to store
            if (ln < 9) {      // Rot_u element (rp, rq)
                float x0 = DX(0), x1 = DX(1), x2 = DX(2);
                float xi[3] = {x0, x1, x2};
                float a2 = x0*x0 + x1*x1 + x2*x2;
                float c, sa, oc; so3c(a2, c, sa, oc);
                float d0 = ((rp==0)?c:0.f) + oc*xi[rp]*xi[0] + sa*skf(xi, rp, 0);
                float d1 = ((rp==1)?c:0.f) + oc*xi[rp]*xi[1] + sa*skf(xi, rp, 1);
                float d2 = ((rp==2)?c:0.f) + oc*xi[rp]*xi[2] + sa*skf(xi, rp, 2);
                sv = d0*s.Rotn[0*3+rq] + d1*s.Rotn[1*3+rq] + d2*s.Rotn[2*3+rq];
            } else if (ln < 15) {   // v_u / p_u element
                int which = (ln - 9) / 3, q3 = (ln - 9) - which*3;
                float xi[3] = {DX(0), DX(1), DX(2)};
                float a2 = xi[0]*xi[0] + xi[1]*xi[1] + xi[2]*xi[2];
                float c, sa, oc; so3c(a2, c, sa, oc);
                float j1 = j1c(a2);
                float y0 = which ? DX(6) : DX(3);
                float y1 = which ? DX(7) : DX(4);
                float y2 = which ? DX(8) : DX(5);
                float J0 = ((q3==0)?sa:0.f) + j1*xi[q3]*xi[0] + oc*skf(xi, q3, 0);
                float J1 = ((q3==1)?sa:0.f) + j1*xi[q3]*xi[1] + oc*skf(xi, q3, 1);
                float J2 = ((q3==2)?sa:0.f) + j1*xi[q3]*xi[2] + oc*skf(xi, q3, 2);
                float x = J0*y0 + J1*y1 + J2*y2;
                float d0 = ((q3==0)?c:0.f) + oc*xi[q3]*xi[0] + sa*skf(xi, q3, 0);
                float d1 = ((q3==1)?c:0.f) + oc*xi[q3]*xi[1] + sa*skf(xi, q3, 1);
                float d2 = ((q3==2)?c:0.f) + oc*xi[q3]*xi[2] + sa*skf(xi, q3, 2);
                const float* src = which ? s.Pn3 : s.Vn;
                sv = d0*src[0] + d1*src[1] + d2*src[2] + x;
            } else if (ln < 24) {   // Rci_u element
                int k = ln - 15, p2 = k/3, q2 = k - p2*3;
                float yi[3] = {DX(15), DX(16), DX(17)};
                float a2 = yi[0]*yi[0] + yi[1]*yi[1] + yi[2]*yi[2];
                float c, sa, oc; so3c(a2, c, sa, oc);
                float e0 = ((p2==0)?c:0.f) + oc*yi[p2]*yi[0] + sa*skf(yi, p2, 0);
                float e1 = ((p2==1)?c:0.f) + oc*yi[p2]*yi[1] + sa*skf(yi, p2, 1);
                float e2 = ((p2==2)?c:0.f) + oc*yi[p2]*yi[2] + sa*skf(yi, p2, 2);
                sv = e0*s.Rci[0*3+q2] + e1*s.Rci[1*3+q2] + e2*s.Rci[2*3+q2];
            } else if (ln < 27) {
                int q = ln - 24;
                sv = s.Bom[q] + DX(9+q);          // b_om_u  (Tci handled below)
            } else if (ln < 30) {
                int q = ln - 27;
                sv = s.Bac[q] + DX(12+q);
            }
            float tciu = 0.f;
            if (ln >= 24 && ln < 27) tciu = s.Tci[ln-24] + DX(18+(ln-24));
            // store updates
            if (ln < 9)        s.Rot[ln] = sv;
            else if (ln < 12)  s.V[ln-9] = sv;
            else if (ln < 15)  s.Pp[ln-12] = sv;
            else if (ln < 24)  s.Rci[ln-15] = sv;
            else if (ln < 27)  { s.Bom[ln-24] = sv; s.Tci[ln-24] = tciu; }
            else if (ln < 30)  s.Bac[ln-27] = sv;
            __syncwarp();
            if (i % 100 == 0) {
                if (ln == 0) {
                    float X[9];
#pragma unroll
                    for (int m = 0; m < 9; ++m) X[m] = s.Rot[m];
                    normrot(X);
#pragma unroll
                    for (int m = 0; m < 9; ++m) s.Rot[m] = X[m];
                }
                if ((i % 1000 == 0) && ln == 1) {
                    float X[9];
#pragma unroll
                    for (int m = 0; m < 9; ++m) X[m] = s.Rci[m];
                    normrot(X);
#pragma unroll
                    for (int m = 0; m < 9; ++m) s.Rci[m] = X[m];
                }
            }
            __syncwarp();
            // next-step propagation using in[nxt]
            const float dtn = s.in[nxt][0] - tc;
            const float gy0 = s.in[nxt][1], gy1 = s.in[nxt][2], gy2 = s.in[nxt][3];
            const float ac0 = s.in[nxt][4], ac1 = s.in[nxt][5], ac2 = s.in[nxt][6];
            const float bo0 = s.Bom[0], bo1 = s.Bom[1], bo2 = s.Bom[2];
            if (ln < 9) {
                float ph[3] = {(gy0-bo0)*dtn, (gy1-bo1)*dtn, (gy2-bo2)*dtn};
                float a2 = ph[0]*ph[0] + ph[1]*ph[1] + ph[2]*ph[2];
                float c, sa, oc; so3c(a2, c, sa, oc);
                float e0 = ((0==rq)?c:0.f) + oc*ph[0]*ph[rq] + sa*skf(ph, 0, rq);
                float e1 = ((1==rq)?c:0.f) + oc*ph[1]*ph[rq] + sa*skf(ph, 1, rq);
                float e2 = ((2==rq)?c:0.f) + oc*ph[2]*ph[rq] + sa*skf(ph, 2, rq);
                s.Rotn[ln] = s.Rot[rp*3+0]*e0 + s.Rot[rp*3+1]*e1 + s.Rot[rp*3+2]*e2;
            } else if (ln < 15) {
                int which = (ln - 9) / 3, q3 = (ln - 9) - which*3;
                float d0 = ac0 - s.Bac[0], d1 = ac1 - s.Bac[1], d2 = ac2 - s.Bac[2];
                float accq = s.Rot[q3*3+0]*d0 + s.Rot[q3*3+1]*d1 + s.Rot[q3*3+2]*d2 + ((q3==2)?GZ:0.f);
                if (which == 0) s.Vn[q3]  = s.V[q3] + accq*dtn;
                else            s.Pn3[q3] = s.Pp[q3] + s.V[q3]*dtn + 0.5f*accq*dtn*dtn;
            } else if (ln < 18) {
                int q = ln - 15;
                s.Om[q] = ((q==0)?gy0:(q==1)?gy1:gy2) - ((q==0)?bo0:(q==1)?bo1:bo2);
            }
            __syncwarp();
            if (ln >= 18 && ln < 21) {
                int q = ln - 18;
                s.vi[q] = s.Rotn[0*3+q]*s.Vn[0] + s.Rotn[1*3+q]*s.Vn[1] + s.Rotn[2*3+q]*s.Vn[2];
            }
            __syncwarp();
            if (ln == 21) {
                float cx1 = s.Tci[2]*s.Om[0] - s.Tci[0]*s.Om[2];
                float cx2 = s.Tci[0]*s.Om[1] - s.Tci[1]*s.Om[0];
                float vb1 = s.Rci[0*3+1]*s.vi[0] + s.Rci[1*3+1]*s.vi[1] + s.Rci[2*3+1]*s.vi[2] + cx1;
                float vb2 = s.Rci[0*3+2]*s.vi[0] + s.Rci[1*3+2]*s.vi[1] + s.Rci[2*3+2]*s.vi[2] + cx2;
                s.r2[0] = -vb1; s.r2[1] = -vb2;
            }
#undef DX
        }
        __syncthreads();
    }

    // ---------- epilogue ----------
    {
        int j = N - 1;
        if (tid < 9)       out[j*9 + tid]             = s.Rot[tid];
        else if (tid < 12) out[9*N  + j*3 + (tid-9)]  = s.V[tid-9];
        else if (tid < 15) out[12*N + j*3 + (tid-12)] = s.Pp[tid-12];
        else if (tid < 18) out[15*N + j*3 + (tid-15)] = s.Bom[tid-15];
        else if (tid < 21) out[18*N + j*3 + (tid-21+3)] = s.Bac[tid-18];
        else if (tid < 30) out[21*N + j*9 + (tid-21)] = s.Rci[tid-21];
        else if (tid < 33) out[30*N + j*3 + (tid-30)] = s.Tci[tid-30];
    }
}

extern "C" void kernel_launch(void* const* d_in, const int* in_sizes, int n_in,
                              void* d_out, int out_size) {
    const float* t    = (const float*)d_in[0];
    const float* u    = (const float*)d_in[1];
    const float* mcov = (const float*)d_in[2];
    const float* vmes = (const float*)d_in[3];
    const float* ang0 = (const float*)d_in[5];
    float* out = (float*)d_out;
    int N = in_sizes[0];
    iekf_kernel<<<1, NT>>>(t, u, mcov, vmes, ang0, out, N);
}

// round 4
// speedup vs baseline: 1.4290x; 1.4290x over previous
#include <cuda_runtime.h>
#include <math.h>

#define NT 512
#define GZ (-9.80665f)

struct SM {
    float P[441], A[441], Pn[441], T9[189], L[108];
    float H[24];        // [2][12] compact cols {3,4,5,9,10,11,15,16,17,18,19,20}
    float G[36];        // [2][18] compact cols {0..5,9..20}
    float GA[42];       // [2][21]
    float HP[42];       // [2][21]
    float S3[3];        // S00 S01 S11
    float r2[2];
    float Rot[9], V[3], Pp[3], Bom[3], Bac[3], Rci[9], Tci[3];
    float Rotn[9], Vn[3], Pn3[3], Om[3], vi[3];
    float in[2][9];     // t, u[6], mcov[2]
};

__device__ __forceinline__ float skf(const float* w, int r, int c) {
    if (r == 0) return (c == 0) ? 0.f : ((c == 1) ? -w[2] : w[1]);
    if (r == 1) return (c == 0) ? w[2] : ((c == 1) ? 0.f : -w[0]);
    return (c == 0) ? -w[1] : ((c == 1) ? w[0] : 0.f);
}
__device__ __forceinline__ float skewrowdot(const float* w, const float* R, int rr, int j) {
    if (rr == 0) return -w[2]*R[3+j] + w[1]*R[6+j];
    if (rr == 1) return  w[2]*R[0+j] - w[0]*R[6+j];
    return -w[1]*R[0+j] + w[0]*R[3+j];
}
__device__ __forceinline__ float SG(int rr, int j) {
    if (rr == 0 && j == 1) return -GZ;
    if (rr == 1 && j == 0) return  GZ;
    return 0.f;
}
__device__ __forceinline__ float sgR(const float* R, int rr, int j) {
    if (rr == 0) return -GZ * R[3+j];
    if (rr == 1) return  GZ * R[0+j];
    return 0.f;
}
__device__ __forceinline__ void so3c(float a2, float& c, float& sa, float& oc) {
    c  = 1.f + a2*(-0.5f      + a2*((1.f/24.f)  + a2*(-1.f/720.f)));
    sa = 1.f + a2*((-1.f/6.f) + a2*((1.f/120.f) + a2*(-1.f/5040.f)));
    oc = 0.5f + a2*((-1.f/24.f) + a2*(1.f/720.f));
}
__device__ __forceinline__ float j1c(float a2) {
    return (1.f/6.f) + a2*((-1.f/120.f) + a2*(1.f/5040.f));
}
__device__ __forceinline__ void mm3(const float* A, const float* B, float* C) {
#pragma unroll
    for (int p = 0; p < 3; ++p)
#pragma unroll
        for (int q = 0; q < 3; ++q)
            C[p*3+q] = A[p*3+0]*B[0*3+q] + A[p*3+1]*B[1*3+q] + A[p*3+2]*B[2*3+q];
}
__device__ __forceinline__ void normrot(float* X) {
    for (int it = 0; it < 8; ++it) {
        float Y[9], Z[9];
#pragma unroll
        for (int p = 0; p < 3; ++p)
#pragma unroll
            for (int q = 0; q < 3; ++q)
                Y[p*3+q] = X[p*3+0]*X[q*3+0] + X[p*3+1]*X[q*3+1] + X[p*3+2]*X[q*3+2];
        mm3(Y, X, Z);
#pragma unroll
        for (int m = 0; m < 9; ++m) X[m] = 1.5f*X[m] - 0.5f*Z[m];
    }
}

__global__ void __launch_bounds__(NT, 1)
iekf_kernel(const float* __restrict__ t, const float* __restrict__ u,
            const float* __restrict__ mc, const float* __restrict__ vmes,
            const float* __restrict__ ang0, float* __restrict__ out, int N)
{
    __shared__ SM s;
    const int tid = threadIdx.x;
    const bool el = (tid < 441);

    // ---------- hoisted per-thread decodes ----------
    int ii = 0, jj = 0, jjT = 0, iib = 0, jl12 = 0, iib12 = 0;
    int am = 2, ar = 0, brx = 0; float asc = 0.f, aqv = 0.f;
    if (el) {
        ii = tid / 21; jj = tid - ii*21;
        jjT = jj*21 + ii; iib = ii*21; jl12 = jj*12; iib12 = ii*12;
        if (ii < 3 && jj < 3)                            { am = 0; ar = ii*3;     brx = jj*3;     asc = 0.001f; }
        else if (ii >= 3 && ii < 6 && jj >= 3 && jj < 6) { am = 0; ar = (ii-3)*3; brx = (jj-3)*3; asc = 0.01f;  }
        else if (ii == jj) {
            am = 1;
            aqv = (ii >= 9 && ii < 12) ? 6e-9f : (ii >= 12 && ii < 15) ? 2e-4f : (ii >= 15) ? 1e-9f : 0.f;
        }
    }
    const bool useT9 = el && (ii < 9);
    // L element for threads 333..440
    const int lt = tid - 333;
    int Lr = 0, Lcc = 0, Lbrr = 0, Lrr = 0, Lbc = 0, Lj = 0;
    if (lt >= 0 && lt < 108) {
        Lr = lt / 12; Lcc = lt - Lr*12;
        Lbrr = Lr / 3; Lrr = Lr - Lbrr*3; Lbc = Lcc / 3; Lj = Lcc - Lbc*3;
    }
    // GA / HP threads 448..489
    int pa = 0, pc = 0;
    if (tid >= 448 && tid < 490) { int k = tid - 448; pa = k/21; pc = k - pa*21; }
    // chain / state lanes (warp 15)
    const int ln = tid - 480;
    const int rp = (ln >= 0 && ln < 9) ? ln/3 : 0;
    const int rq = (ln >= 0 && ln < 9) ? ln - rp*3 : 0;
    int ha = 0, hcc = 0, hbb = 0, hj = 0;
    if (ln >= 0 && ln < 24) { ha = ln/12; hcc = ln - ha*12; hbb = hcc/3; hj = hcc - hbb*3; }

    // ---------- prologue ----------
    float tprev = t[0];
    for (int k = tid; k < 441; k += NT) {
        int i = k / 21, j = k - i*21;
        float pv = 0.f;
        if (i == j) {
            if (i < 2) pv = 0.001f;
            else if (i >= 3 && i < 5) pv = 0.1f;
            else if (i >= 9 && i < 12) pv = 0.006f;
            else if (i >= 12 && i < 15) pv = 0.004f;
            else if (i >= 15 && i < 18) pv = 1e-6f;
            else if (i >= 18) pv = 0.005f;
        }
        s.P[k] = pv;
    }
    if (tid < 9) {
        float v;
        if (tid == 0) v = t[1];
        else if (tid < 7) v = u[6 + (tid-1)];
        else v = mc[2 + (tid-7)];
        s.in[1][tid] = v;
    }
    if (tid == 0) {
        float a0 = ang0[0], a1 = ang0[1], a2 = ang0[2];
        float cr = cosf(a0), sr = sinf(a0), cp = cosf(a1), sp = sinf(a1);
        float cy = cosf(a2), sy = sinf(a2);
        float Rx[9] = {1,0,0, 0,cr,-sr, 0,sr,cr};
        float Ry[9] = {cp,0,sp, 0,1,0, -sp,0,cp};
        float Rz[9] = {cy,-sy,0, sy,cy,0, 0,0,1};
        float T[9], R0[9];
        mm3(Rz, Ry, T); mm3(T, Rx, R0);
#pragma unroll
        for (int m = 0; m < 9; ++m) { s.Rot[m] = R0[m]; s.Rci[m] = (m==0||m==4||m==8) ? 1.f : 0.f; }
#pragma unroll
        for (int q = 0; q < 3; ++q) {
            s.V[q] = vmes[q]; s.Pp[q] = 0.f; s.Bom[q] = 0.f; s.Bac[q] = 0.f; s.Tci[q] = 0.f;
        }
    }
    __syncthreads();

    // ---------- main loop ----------
    for (int i = 1; i < N; ++i) {
        const int cur = i & 1;
        const int nxt = cur ^ 1;
        const float tc = s.in[cur][0];
        const float dt = tc - tprev;
        tprev = tc;
        const float dt2 = dt*dt;
        const float dt3 = dt2*dt;

        // ======== PHASE 1: A, L, out-STG, prefetch LDG, measurement chain ========
        float pf = 0.f;
        if (el) {
            float gq = 0.f;
            if (am == 0) {
                float d = s.Rot[ar]*s.Rot[brx] + s.Rot[ar+1]*s.Rot[brx+1] + s.Rot[ar+2]*s.Rot[brx+2];
                gq = asc * dt2 * d;
            } else if (am == 1) gq = aqv * dt2;
            s.A[tid] = s.P[tid] + gq;
        }
        if (lt >= 0 && lt < 108) {     // L closed form: Phi - I
            float v = 0.f;
            if (Lbrr == 0) {
                if (Lbc == 2) v = -dt * s.Rot[Lrr*3+Lj];
            } else if (Lbrr == 1) {
                if (Lbc == 0)      v = dt * SG(Lrr, Lj);
                else if (Lbc == 2) v = -dt*skewrowdot(s.V, s.Rot, Lrr, Lj) - 0.5f*dt2*sgR(s.Rot, Lrr, Lj);
                else if (Lbc == 3) v = -dt * s.Rot[Lrr*3+Lj];
            } else {
                if (Lbc == 0)      v = 0.5f*dt2*SG(Lrr, Lj);
                else if (Lbc == 1) v = (Lrr == Lj) ? dt : 0.f;
                else if (Lbc == 2) v = -dt*skewrowdot(s.Pp, s.Rot, Lrr, Lj)
                                       - 0.5f*dt2*skewrowdot(s.V, s.Rot, Lrr, Lj)
                                       - (dt3*(1.f/6.f))*sgR(s.Rot, Lrr, Lj);
                else               v = -0.5f*dt2*s.Rot[Lrr*3+Lj];
            }
            s.L[lt] = v;
        }
        if (tid < 33) {   // outputs of step i-1
            int j = i - 1;
            if (tid < 9)       out[j*9 + tid]             = s.Rot[tid];
            else if (tid < 12) out[9*N  + j*3 + (tid-9)]  = s.V[tid-9];
            else if (tid < 15) out[12*N + j*3 + (tid-12)] = s.Pp[tid-12];
            else if (tid < 18) out[15*N + j*3 + (tid-15)] = s.Bom[tid-15];
            else if (tid < 21) out[18*N + j*3 + (tid-18)] = s.Bac[tid-18];
            else if (tid < 30) out[21*N + j*9 + (tid-21)] = s.Rci[tid-21];
            else               out[30*N + j*3 + (tid-30)] = s.Tci[tid-30];
        }
        if (tid >= 448 && tid < 457) {    // prefetch inputs for step i+1
            int nx = i + 1, q = tid - 448;
            if (nx < N) {
                if (q == 0) pf = t[nx];
                else if (q < 7) pf = u[nx*6 + (q-1)];
                else pf = mc[nx*2 + (q-7)];
            }
        }
        if (tid >= 480) {   // measurement chain: prop -> vi -> H,r -> G
            const float gy0 = s.in[cur][1], gy1 = s.in[cur][2], gy2 = s.in[cur][3];
            const float ac0 = s.in[cur][4], ac1 = s.in[cur][5], ac2 = s.in[cur][6];
            if (ln < 9) {
                float ph[3] = {(gy0-s.Bom[0])*dt, (gy1-s.Bom[1])*dt, (gy2-s.Bom[2])*dt};
                float a2 = ph[0]*ph[0] + ph[1]*ph[1] + ph[2]*ph[2];
                float c, sa, oc; so3c(a2, c, sa, oc);
                float e0 = ((0==rq)?c:0.f) + oc*ph[0]*ph[rq] + sa*skf(ph, 0, rq);
                float e1 = ((1==rq)?c:0.f) + oc*ph[1]*ph[rq] + sa*skf(ph, 1, rq);
                float e2 = ((2==rq)?c:0.f) + oc*ph[2]*ph[rq] + sa*skf(ph, 2, rq);
                s.Rotn[ln] = s.Rot[rp*3+0]*e0 + s.Rot[rp*3+1]*e1 + s.Rot[rp*3+2]*e2;
            } else if (ln < 15) {
                int which = (ln - 9) / 3, q3 = (ln - 9) - which*3;
                float d0 = ac0 - s.Bac[0], d1 = ac1 - s.Bac[1], d2 = ac2 - s.Bac[2];
                float accq = s.Rot[q3*3+0]*d0 + s.Rot[q3*3+1]*d1 + s.Rot[q3*3+2]*d2 + ((q3==2)?GZ:0.f);
                if (which == 0) s.Vn[q3]  = s.V[q3] + accq*dt;
                else            s.Pn3[q3] = s.Pp[q3] + s.V[q3]*dt + 0.5f*accq*dt2;
            } else if (ln < 18) {
                int q = ln - 15;
                s.Om[q] = ((q==0)?gy0:(q==1)?gy1:gy2) - s.Bom[q];
            }
            __syncwarp();
            if (ln >= 18 && ln < 21) {
                int q = ln - 18;
                s.vi[q] = s.Rotn[q]*s.Vn[0] + s.Rotn[3+q]*s.Vn[1] + s.Rotn[6+q]*s.Vn[2];
            }
            __syncwarp();
            if (ln < 24) {   // H
                float hv;
                if (hbb == 0) {
                    hv = s.Rotn[hj*3+0]*s.Rci[ha+1] + s.Rotn[hj*3+1]*s.Rci[3+ha+1] + s.Rotn[hj*3+2]*s.Rci[6+ha+1];
                } else if (hbb == 1) {
                    hv = skf(s.Tci, ha+1, hj);
                } else if (hbb == 2) {
                    hv = s.Rci[ha+1]*skf(s.vi,0,hj) + s.Rci[3+ha+1]*skf(s.vi,1,hj) + s.Rci[6+ha+1]*skf(s.vi,2,hj);
                } else {
                    hv = -skf(s.Om, ha+1, hj);
                }
                s.H[ha*12+hcc] = hv;
            } else if (ln < 26) {   // r
                int a = ln - 24;
                float cxa = (a==0) ? (s.Tci[2]*s.Om[0] - s.Tci[0]*s.Om[2])
                                   : (s.Tci[0]*s.Om[1] - s.Tci[1]*s.Om[0]);
                float vb = s.Rci[a+1]*s.vi[0] + s.Rci[3+a+1]*s.vi[1] + s.Rci[6+a+1]*s.vi[2] + cxa;
                s.r2[a] = -vb;
            }
            __syncwarp();
            if (ln < 18) {   // G = H*Phi, both rows of compact col m
                int m = ln;
                float g0, g1;
                if (m == 0)      { float f = dt*SG(1,0); g0 = s.H[1]*f;  g1 = s.H[13]*f; }
                else if (m == 1) { float f = dt*SG(0,1); g0 = s.H[0]*f;  g1 = s.H[12]*f; }
                else if (m == 2) { g0 = 0.f; g1 = 0.f; }
                else if (m < 6)  { g0 = s.H[m-3]; g1 = s.H[12+m-3]; }
                else if (m < 9) {
                    int j = m - 6;
                    float l0 = -dt*skewrowdot(s.V, s.Rot, 0, j) - 0.5f*dt2*sgR(s.Rot, 0, j);
                    float l1 = -dt*skewrowdot(s.V, s.Rot, 1, j) - 0.5f*dt2*sgR(s.Rot, 1, j);
                    float l2 = -dt*skewrowdot(s.V, s.Rot, 2, j) - 0.5f*dt2*sgR(s.Rot, 2, j);
                    g0 = s.H[3+j]  + s.H[0]*l0  + s.H[1]*l1  + s.H[2]*l2;
                    g1 = s.H[15+j] + s.H[12]*l0 + s.H[13]*l1 + s.H[14]*l2;
                } else if (m < 12) {
                    int j = m - 9;
                    float l0 = -dt*s.Rot[j], l1 = -dt*s.Rot[3+j], l2 = -dt*s.Rot[6+j];
                    g0 = s.H[0]*l0  + s.H[1]*l1  + s.H[2]*l2;
                    g1 = s.H[12]*l0 + s.H[13]*l1 + s.H[14]*l2;
                } else { g0 = s.H[m-6]; g1 = s.H[12+m-6]; }
                s.G[m] = g0; s.G[18+m] = g1;
            }
        }
        __syncthreads();

        // ======== PHASE 2: T9 = rows 0..8 of Phi@A ; GA = G@A ========
        if (tid < 189) {
            float a = s.A[tid];
#pragma unroll
            for (int cc = 0; cc < 12; ++cc) {
                const int col = (cc < 6) ? cc : cc + 3;
                a += s.L[iib12+cc] * s.A[col*21 + jj];
            }
            s.T9[tid] = a;
        }
        if (tid >= 448 && tid < 490) {
            float acc = 0.f;
#pragma unroll
            for (int m = 0; m < 18; ++m) {
                const int col = (m < 6) ? m : m + 3;
                acc += s.G[pa*18+m] * s.A[col*21 + pc];
            }
            s.GA[pa*21+pc] = acc;
        }
        __syncthreads();

        // ======== PHASE 3: Pn ; HP = GA@Phi^T ; S = GA@G^T + Rm ========
        if (el) {
            float b = useT9 ? s.T9[tid] : s.A[tid];
            if (jj < 9) {
#pragma unroll
                for (int cc = 0; cc < 12; ++cc) {
                    const int col = (cc < 6) ? cc : cc + 3;
                    float brc = useT9 ? s.T9[iib+col] : s.A[iib+col];
                    b += brc * s.L[jl12+cc];
                }
            }
            s.Pn[tid] = b;
        }
        if (tid >= 448 && tid < 490) {
            float hp = s.GA[pa*21+pc];
            if (pc < 9) {
#pragma unroll
                for (int cc = 0; cc < 12; ++cc) {
                    const int col = (cc < 6) ? cc : cc + 3;
                    hp += s.GA[pa*21+col] * s.L[pc*12+cc];
                }
            }
            s.HP[pa*21+pc] = hp;
        }
        if (tid >= 490 && tid < 493) {
            int m = tid - 490;
            int a = (m == 2) ? 1 : 0;
            int b = (m == 0) ? 0 : 1;
            float acc = 0.f;
#pragma unroll
            for (int mm = 0; mm < 18; ++mm) {
                const int col = (mm < 6) ? mm : mm + 3;
                acc += s.GA[a*21+col] * s.G[b*18+mm];
            }
            if (a == b) acc += s.in[cur][7+a];
            s.S3[m] = acc;
        }
        __syncthreads();

        // ======== PHASE 4: P Joseph update ; state update ; prefetch STS ========
        if (el) {
            const float S00 = s.S3[0], S01 = s.S3[1], S11 = s.S3[2];
            const float idet = 1.f / (S00*S11 - S01*S01);
            const float Si00 = S11*idet, Si01 = -S01*idet, Si11 = S00*idet;
            const float hp0i = s.HP[ii], hp1i = s.HP[21+ii];
            const float hp0j = s.HP[jj], hp1j = s.HP[21+jj];
            const float Ki0 = Si00*hp0i + Si01*hp1i, Ki1 = Si01*hp0i + Si11*hp1i;
            const float Kj0 = Si00*hp0j + Si01*hp1j, Kj1 = Si01*hp0j + Si11*hp1j;
            const float KSi0 = Ki0*S00 + Ki1*S01, KSi1 = Ki0*S01 + Ki1*S11;
            float v = 0.5f*(s.Pn[tid] + s.Pn[jjT])
                    - (Ki0*hp0j + Ki1*hp1j) - (Kj0*hp0i + Kj1*hp1i)
                    + (KSi0*Kj0 + KSi1*Kj1);
            s.P[tid] = v;
        }
        if (tid >= 448 && tid < 457) {
            if (i + 1 < N) s.in[nxt][tid-448] = pf;
        }
        if (tid >= 480) {
            const float S00 = s.S3[0], S01 = s.S3[1], S11 = s.S3[2];
            const float idet = 1.f / (S00*S11 - S01*S01);
            const float Si00 = S11*idet, Si01 = -S01*idet, Si11 = S00*idet;
            const float r0 = s.r2[0], r1 = s.r2[1];
            const float w0 = Si00*r0 + Si01*r1, w1 = Si01*r0 + Si11*r1;
#define DX(c) (s.HP[(c)]*w0 + s.HP[21+(c)]*w1)
            float sv = 0.f;
            float tciu = 0.f;
            if (ln < 9) {
                float xi[3] = {DX(0), DX(1), DX(2)};
                float a2 = xi[0]*xi[0] + xi[1]*xi[1] + xi[2]*xi[2];
                float c, sa, oc; so3c(a2, c, sa, oc);
                float d0 = ((rp==0)?c:0.f) + oc*xi[rp]*xi[0] + sa*skf(xi, rp, 0);
                float d1 = ((rp==1)?c:0.f) + oc*xi[rp]*xi[1] + sa*skf(xi, rp, 1);
                float d2 = ((rp==2)?c:0.f) + oc*xi[rp]*xi[2] + sa*skf(xi, rp, 2);
                sv = d0*s.Rotn[rq] + d1*s.Rotn[3+rq] + d2*s.Rotn[6+rq];
            } else if (ln < 15) {
                int which = (ln - 9) / 3, q3 = (ln - 9) - which*3;
                float xi[3] = {DX(0), DX(1), DX(2)};
                float a2 = xi[0]*xi[0] + xi[1]*xi[1] + xi[2]*xi[2];
                float c, sa, oc; so3c(a2, c, sa, oc);
                float j1 = j1c(a2);
                float y0 = which ? DX(6) : DX(3);
                float y1 = which ? DX(7) : DX(4);
                float y2 = which ? DX(8) : DX(5);
                float J0 = ((q3==0)?sa:0.f) + j1*xi[q3]*xi[0] + oc*skf(xi, q3, 0);
                float J1 = ((q3==1)?sa:0.f) + j1*xi[q3]*xi[1] + oc*skf(xi, q3, 1);
                float J2 = ((q3==2)?sa:0.f) + j1*xi[q3]*xi[2] + oc*skf(xi, q3, 2);
                float x = J0*y0 + J1*y1 + J2*y2;
                float d0 = ((q3==0)?c:0.f) + oc*xi[q3]*xi[0] + sa*skf(xi, q3, 0);
                float d1 = ((q3==1)?c:0.f) + oc*xi[q3]*xi[1] + sa*skf(xi, q3, 1);
                float d2 = ((q3==2)?c:0.f) + oc*xi[q3]*xi[2] + sa*skf(xi, q3, 2);
                const float* src = which ? s.Pn3 : s.Vn;
                sv = d0*src[0] + d1*src[1] + d2*src[2] + x;
            } else if (ln < 24) {
                int k = ln - 15, p2 = k/3, q2 = k - p2*3;
                float yi[3] = {DX(15), DX(16), DX(17)};
                float a2 = yi[0]*yi[0] + yi[1]*yi[1] + yi[2]*yi[2];
                float c, sa, oc; so3c(a2, c, sa, oc);
                float e0 = ((p2==0)?c:0.f) + oc*yi[p2]*yi[0] + sa*skf(yi, p2, 0);
                float e1 = ((p2==1)?c:0.f) + oc*yi[p2]*yi[1] + sa*skf(yi, p2, 1);
                float e2 = ((p2==2)?c:0.f) + oc*yi[p2]*yi[2] + sa*skf(yi, p2, 2);
                sv = e0*s.Rci[q2] + e1*s.Rci[3+q2] + e2*s.Rci[6+q2];
            } else if (ln < 27) {
                int q = ln - 24;
                sv = s.Bom[q] + DX(9+q);
                tciu = s.Tci[q] + DX(18+q);
            } else if (ln < 30) {
                int q = ln - 27;
                sv = s.Bac[q] + DX(12+q);
            }
#undef DX
            if (ln < 9)        s.Rot[ln] = sv;
            else if (ln < 12)  s.V[ln-9] = sv;
            else if (ln < 15)  s.Pp[ln-12] = sv;
            else if (ln < 24)  s.Rci[ln-15] = sv;
            else if (ln < 27)  { s.Bom[ln-24] = sv; s.Tci[ln-24] = tciu; }
            else if (ln < 30)  s.Bac[ln-27] = sv;
            __syncwarp();
            if (i % 100 == 0) {
                if (ln == 0) {
                    float X[9];
#pragma unroll
                    for (int m = 0; m < 9; ++m) X[m] = s.Rot[m];
                    normrot(X);
#pragma unroll
                    for (int m = 0; m < 9; ++m) s.Rot[m] = X[m];
                }
                if ((i % 1000 == 0) && ln == 1) {
                    float X[9];
#pragma unroll
                    for (int m = 0; m < 9; ++m) X[m] = s.Rci[m];
                    normrot(X);
#pragma unroll
                    for (int m = 0; m < 9; ++m) s.Rci[m] = X[m];
                }
            }
        }
        __syncthreads();
    }

    // ---------- epilogue ----------
    {
        int j = N - 1;
        if (tid < 9)       out[j*9 + tid]             = s.Rot[tid];
        else if (tid < 12) out[9*N  + j*3 + (tid-9)]  = s.V[tid-9];
        else if (tid < 15) out[12*N + j*3 + (tid-12)] = s.Pp[tid-12];
        else if (tid < 18) out[15*N + j*3 + (tid-15)] = s.Bom[tid-15];
        else if (tid < 21) out[18*N + j*3 + (tid-18)] = s.Bac[tid-18];
        else if (tid < 30) out[21*N + j*9 + (tid-21)] = s.Rci[tid-21];
        else if (tid < 33) out[30*N + j*3 + (tid-30)] = s.Tci[tid-30];
    }
}

extern "C" void kernel_launch(void* const* d_in, const int* in_sizes, int n_in,
                              void* d_out, int out_size) {
    const float* t    = (const float*)d_in[0];
    const float* u    = (const float*)d_in[1];
    const float* mcov = (const float*)d_in[2];
    const float* vmes = (const float*)d_in[3];
    const float* ang0 = (const float*)d_in[5];
    float* out = (float*)d_out;
    int N = in_sizes[0];
    iekf_kernel<<<1, NT>>>(t, u, mcov, vmes, ang0, out, N);
}

// round 5
// speedup vs baseline: 2.6369x; 1.8452x over previous
#include <cuda_runtime.h>
#include <math.h>

#define NT 128
#define GZ (-9.80665f)

struct SM {
    float P[441], A[441], Pn[441], T9[189], L[108];
    float G[36], GA[42], HP[42], S3[3];
    float mir[33];     // Rot[0..8], V, Pp, Bom, Bac, Rci[21..29], Tci[30..32]
    float in[2][9];    // t, u[6], mcov[2]
};

__device__ __forceinline__ float skf(const float* w, int r, int c) {
    if (r == 0) return (c == 0) ? 0.f : ((c == 1) ? -w[2] : w[1]);
    if (r == 1) return (c == 0) ? w[2] : ((c == 1) ? 0.f : -w[0]);
    return (c == 0) ? -w[1] : ((c == 1) ? w[0] : 0.f);
}
__device__ __forceinline__ float skewrowdot(const float* w, const float* R, int rr, int j) {
    if (rr == 0) return -w[2]*R[3+j] + w[1]*R[6+j];
    if (rr == 1) return  w[2]*R[0+j] - w[0]*R[6+j];
    return -w[1]*R[0+j] + w[0]*R[3+j];
}
__device__ __forceinline__ float SG(int rr, int j) {
    if (rr == 0 && j == 1) return -GZ;
    if (rr == 1 && j == 0) return  GZ;
    return 0.f;
}
__device__ __forceinline__ float sgR(const float* R, int rr, int j) {
    if (rr == 0) return -GZ * R[3+j];
    if (rr == 1) return  GZ * R[0+j];
    return 0.f;
}
__device__ __forceinline__ void so3c(float a2, float& c, float& sa, float& oc) {
    c  = 1.f + a2*(-0.5f      + a2*((1.f/24.f)  + a2*(-1.f/720.f)));
    sa = 1.f + a2*((-1.f/6.f) + a2*((1.f/120.f) + a2*(-1.f/5040.f)));
    oc = 0.5f + a2*((-1.f/24.f) + a2*(1.f/720.f));
}
__device__ __forceinline__ float j1c(float a2) {
    return (1.f/6.f) + a2*((-1.f/120.f) + a2*(1.f/5040.f));
}
__device__ __forceinline__ void mm3(const float* A, const float* B, float* C) {
#pragma unroll
    for (int p = 0; p < 3; ++p)
#pragma unroll
        for (int q = 0; q < 3; ++q)
            C[p*3+q] = A[p*3+0]*B[0*3+q] + A[p*3+1]*B[1*3+q] + A[p*3+2]*B[2*3+q];
}
__device__ __forceinline__ void normrot(float* X) {
    for (int it = 0; it < 8; ++it) {
        float Y[9], Z[9];
#pragma unroll
        for (int p = 0; p < 3; ++p)
#pragma unroll
            for (int q = 0; q < 3; ++q)
                Y[p*3+q] = X[p*3+0]*X[q*3+0] + X[p*3+1]*X[q*3+1] + X[p*3+2]*X[q*3+2];
        mm3(Y, X, Z);
#pragma unroll
        for (int m = 0; m < 9; ++m) X[m] = 1.5f*X[m] - 0.5f*Z[m];
    }
}

__global__ void __launch_bounds__(NT, 1)
iekf_kernel(const float* __restrict__ t, const float* __restrict__ u,
            const float* __restrict__ mc, const float* __restrict__ vmes,
            const float* __restrict__ ang0, float* __restrict__ out, int N)
{
    __shared__ SM s;
    const int tid = threadIdx.x;

    // ---------- hoisted per-slot decodes (4 P-elements per thread) ----------
    bool eV[4]; int eII[4], eJJ[4], eJJT[4], eIIB[4], eJJ12[4];
    int eAm[4], eAr[4], eBrx[4]; float eAsc[4], eAqv[4]; bool eT9[4];
#pragma unroll
    for (int sl = 0; sl < 4; ++sl) {
        int e = tid + sl*128;
        eV[sl] = (e < 441);
        int ii = 0, jj = 0;
        if (eV[sl]) { ii = e/21; jj = e - ii*21; }
        eII[sl]=ii; eJJ[sl]=jj; eJJT[sl]=jj*21+ii; eIIB[sl]=ii*21; eJJ12[sl]=jj*12;
        eT9[sl] = (ii < 9);
        int am = 2, ar = 0, brx = 0; float asc = 0.f, aqv = 0.f;
        if (ii<3 && jj<3)                        { am=0; ar=ii*3;     brx=jj*3;     asc=0.001f; }
        else if (ii>=3&&ii<6&&jj>=3&&jj<6)       { am=0; ar=(ii-3)*3; brx=(jj-3)*3; asc=0.01f;  }
        else if (ii==jj) { am=1; aqv = (ii>=9&&ii<12)?6e-9f:(ii>=12&&ii<15)?2e-4f:(ii>=15)?1e-9f:0.f; }
        eAm[sl]=am; eAr[sl]=ar; eBrx[sl]=brx; eAsc[sl]=asc; eAqv[sl]=aqv;
    }
    // T9 slots
    const int t9aR = tid/21, t9aC = tid - (tid/21)*21, t9aR12 = t9aR*12;
    const int t9b = tid + 128; const bool t9bV = (t9b < 189);
    int t9bR = 0, t9bC = 0;
    if (t9bV) { t9bR = t9b/21; t9bC = t9b - t9bR*21; }
    const int t9bR12 = t9bR*12;
    // GA
    const bool gaV = (tid >= 64 && tid < 106);
    int gaA = 0, gaC = 0;
    if (gaV) { int k = tid - 64; gaA = k/21; gaC = k - gaA*21; }
    // HP
    const bool hpV = (tid >= 86);
    int hpA = 0, hpC = 0;
    if (hpV) { int k = tid - 86; hpA = k/21; hpC = k - hpA*21; }
    // L
    const bool lV = (tid < 108);
    int Lbrr = 0, Lrr = 0, Lbc = 0, Lj = 0;
    if (lV) {
        int r = tid/12, cc = tid - r*12;
        Lbrr = r/3; Lrr = r - Lbrr*3; Lbc = cc/3; Lj = cc - Lbc*3;
    }
    // out pointer
    float* outPtr = out; int outStride = 0;
    if (tid < 9)       { outPtr = out + tid;              outStride = 9; }
    else if (tid < 12) { outPtr = out + 9*N  + (tid-9);   outStride = 3; }
    else if (tid < 15) { outPtr = out + 12*N + (tid-12);  outStride = 3; }
    else if (tid < 18) { outPtr = out + 15*N + (tid-15);  outStride = 3; }
    else if (tid < 21) { outPtr = out + 18*N + (tid-18);  outStride = 3; }
    else if (tid < 30) { outPtr = out + 21*N + (tid-21);  outStride = 9; }
    else if (tid < 33) { outPtr = out + 30*N + (tid-30);  outStride = 3; }
    // prefetch pointer (lanes 64..72)
    const float* pfPtr = t; int pfStride = 0;
    const bool pfV = (tid >= 64 && tid < 73);
    if (pfV) {
        int q = tid - 64;
        if (q == 0)      { pfPtr = t  + 2;            pfStride = 1; }
        else if (q < 7)  { pfPtr = u  + 12 + (q-1);   pfStride = 6; }
        else             { pfPtr = mc + 4  + (q-7);   pfStride = 2; }
    }

    // chain-lane persistent registers
    float Rg[9], Vg[3], Ppg[3], Bomg[3], Bacg[3], Rcig[9], Tcig[3];
    float rn[9], vn[3], pn3[3], omg[3], vig[3], r2g[2];

    // ---------- prologue ----------
    float tprev = t[0];
#pragma unroll
    for (int sl = 0; sl < 4; ++sl) if (eV[sl]) {
        int e = tid + sl*128;
        int ii = eII[sl], jj = eJJ[sl];
        float pv = 0.f;
        if (ii == jj) {
            if (ii < 2) pv = 0.001f;
            else if (ii >= 3 && ii < 5) pv = 0.1f;
            else if (ii >= 9 && ii < 12) pv = 0.006f;
            else if (ii >= 12 && ii < 15) pv = 0.004f;
            else if (ii >= 15 && ii < 18) pv = 1e-6f;
            else if (ii >= 18) pv = 0.005f;
        }
        s.P[e] = pv;
    }
    if (tid < 9) {
        float v;
        if (tid == 0) v = t[1];
        else if (tid < 7) v = u[6 + (tid-1)];
        else v = mc[2 + (tid-7)];
        s.in[1][tid] = v;
    }
    if (tid == 96) {
        float a0 = ang0[0], a1 = ang0[1], a2 = ang0[2];
        float cr = cosf(a0), sr = sinf(a0), cp = cosf(a1), sp = sinf(a1);
        float cy = cosf(a2), sy = sinf(a2);
        float Rx[9] = {1,0,0, 0,cr,-sr, 0,sr,cr};
        float Ry[9] = {cp,0,sp, 0,1,0, -sp,0,cp};
        float Rz[9] = {cy,-sy,0, sy,cy,0, 0,0,1};
        float T[9];
        mm3(Rz, Ry, T); mm3(T, Rx, Rg);
#pragma unroll
        for (int m = 0; m < 9; ++m) Rcig[m] = (m==0||m==4||m==8) ? 1.f : 0.f;
#pragma unroll
        for (int q = 0; q < 3; ++q) {
            Vg[q] = vmes[q]; Ppg[q] = 0.f; Bomg[q] = 0.f; Bacg[q] = 0.f; Tcig[q] = 0.f;
        }
#pragma unroll
        for (int m = 0; m < 9; ++m) s.mir[m] = Rg[m];
#pragma unroll
        for (int q = 0; q < 3; ++q) {
            s.mir[9+q] = Vg[q]; s.mir[12+q] = Ppg[q]; s.mir[15+q] = Bomg[q];
            s.mir[18+q] = Bacg[q]; s.mir[30+q] = Tcig[q];
        }
#pragma unroll
        for (int m = 0; m < 9; ++m) s.mir[21+m] = Rcig[m];
    }
    __syncthreads();

    // ---------- main loop ----------
    for (int i = 1; i < N; ++i) {
        const int cur = i & 1;
        const int nxt = cur ^ 1;
        const float tc = s.in[cur][0];
        const float dt = tc - tprev;
        tprev = tc;
        const float dt2 = dt*dt;
        const float dt3 = dt2*dt;

        // ======== PHASE 1: A, L, out-STG, prefetch LDG, chain(H,G,r) ========
        float pf = 0.f;
#pragma unroll
        for (int sl = 0; sl < 4; ++sl) if (eV[sl]) {
            int e = tid + sl*128;
            float gq = 0.f;
            if (eAm[sl] == 0) {
                float d = s.mir[eAr[sl]]*s.mir[eBrx[sl]] + s.mir[eAr[sl]+1]*s.mir[eBrx[sl]+1]
                        + s.mir[eAr[sl]+2]*s.mir[eBrx[sl]+2];
                gq = eAsc[sl] * dt2 * d;
            } else if (eAm[sl] == 1) gq = eAqv[sl] * dt2;
            s.A[e] = s.P[e] + gq;
        }
        if (lV) {
            const float* Rm = s.mir;          // Rot
            const float* Vm = s.mir + 9;      // V
            const float* Pm = s.mir + 12;     // Pp
            float v = 0.f;
            if (Lbrr == 0) {
                if (Lbc == 2) v = -dt * Rm[Lrr*3+Lj];
            } else if (Lbrr == 1) {
                if (Lbc == 0)      v = dt * SG(Lrr, Lj);
                else if (Lbc == 2) v = -dt*skewrowdot(Vm, Rm, Lrr, Lj) - 0.5f*dt2*sgR(Rm, Lrr, Lj);
                else if (Lbc == 3) v = -dt * Rm[Lrr*3+Lj];
            } else {
                if (Lbc == 0)      v = 0.5f*dt2*SG(Lrr, Lj);
                else if (Lbc == 1) v = (Lrr == Lj) ? dt : 0.f;
                else if (Lbc == 2) v = -dt*skewrowdot(Pm, Rm, Lrr, Lj)
                                       - 0.5f*dt2*skewrowdot(Vm, Rm, Lrr, Lj)
                                       - (dt3*(1.f/6.f))*sgR(Rm, Lrr, Lj);
                else               v = -0.5f*dt2*Rm[Lrr*3+Lj];
            }
            s.L[tid] = v;
        }
        if (tid < 33) { *outPtr = s.mir[tid]; outPtr += outStride; }
        if (pfV && (i + 1 < N)) { pf = *pfPtr; pfPtr += pfStride; }
        if (tid == 96) {
            const float gy0 = s.in[cur][1], gy1 = s.in[cur][2], gy2 = s.in[cur][3];
            const float ac0 = s.in[cur][4], ac1 = s.in[cur][5], ac2 = s.in[cur][6];
            omg[0] = gy0 - Bomg[0]; omg[1] = gy1 - Bomg[1]; omg[2] = gy2 - Bomg[2];
            float phi[3] = {omg[0]*dt, omg[1]*dt, omg[2]*dt};
            float a2 = phi[0]*phi[0] + phi[1]*phi[1] + phi[2]*phi[2];
            float c, sa, oc; so3c(a2, c, sa, oc);
            float E[9];
#pragma unroll
            for (int p = 0; p < 3; ++p)
#pragma unroll
                for (int q = 0; q < 3; ++q)
                    E[p*3+q] = ((p==q)?c:0.f) + oc*phi[p]*phi[q] + sa*skf(phi, p, q);
#pragma unroll
            for (int p = 0; p < 3; ++p)
#pragma unroll
                for (int q = 0; q < 3; ++q)
                    rn[p*3+q] = Rg[p*3+0]*E[0*3+q] + Rg[p*3+1]*E[1*3+q] + Rg[p*3+2]*E[2*3+q];
            float d0 = ac0 - Bacg[0], d1 = ac1 - Bacg[1], d2 = ac2 - Bacg[2];
            float acc[3];
#pragma unroll
            for (int q = 0; q < 3; ++q)
                acc[q] = Rg[q*3+0]*d0 + Rg[q*3+1]*d1 + Rg[q*3+2]*d2 + ((q==2)?GZ:0.f);
#pragma unroll
            for (int q = 0; q < 3; ++q) {
                vn[q]  = Vg[q] + acc[q]*dt;
                pn3[q] = Ppg[q] + Vg[q]*dt + 0.5f*acc[q]*dt2;
            }
#pragma unroll
            for (int q = 0; q < 3; ++q)
                vig[q] = rn[0*3+q]*vn[0] + rn[1*3+q]*vn[1] + rn[2*3+q]*vn[2];
            float h[24];
#pragma unroll
            for (int a = 0; a < 2; ++a)
#pragma unroll
                for (int j = 0; j < 3; ++j) {
                    h[a*12 + j]     = rn[j*3+0]*Rcig[a+1] + rn[j*3+1]*Rcig[3+a+1] + rn[j*3+2]*Rcig[6+a+1];
                    h[a*12 + 3 + j] = skf(Tcig, a+1, j);
                    h[a*12 + 6 + j] = Rcig[a+1]*skf(vig,0,j) + Rcig[3+a+1]*skf(vig,1,j) + Rcig[6+a+1]*skf(vig,2,j);
                    h[a*12 + 9 + j] = -skf(omg, a+1, j);
                }
            float Lv[9];
#pragma unroll
            for (int rr = 0; rr < 3; ++rr)
#pragma unroll
                for (int j = 0; j < 3; ++j)
                    Lv[rr*3+j] = -dt*skewrowdot(Vg, Rg, rr, j) - 0.5f*dt2*sgR(Rg, rr, j);
            float g[36];
#pragma unroll
            for (int a = 0; a < 2; ++a) {
                g[a*18+0] =  h[a*12+1]*(dt*GZ);
                g[a*18+1] = -h[a*12+0]*(dt*GZ);
                g[a*18+2] = 0.f;
#pragma unroll
                for (int j = 0; j < 3; ++j) g[a*18+3+j] = h[a*12+j];
#pragma unroll
                for (int j = 0; j < 3; ++j)
                    g[a*18+6+j] = h[a*12+3+j] + h[a*12+0]*Lv[j] + h[a*12+1]*Lv[3+j] + h[a*12+2]*Lv[6+j];
#pragma unroll
                for (int j = 0; j < 3; ++j)
                    g[a*18+9+j] = -dt*(h[a*12+0]*Rg[j] + h[a*12+1]*Rg[3+j] + h[a*12+2]*Rg[6+j]);
#pragma unroll
                for (int m = 12; m < 18; ++m) g[a*18+m] = h[a*12+m-6];
            }
#pragma unroll
            for (int m = 0; m < 36; ++m) s.G[m] = g[m];
            r2g[0] = -(Rcig[1]*vig[0] + Rcig[4]*vig[1] + Rcig[7]*vig[2] + (Tcig[2]*omg[0] - Tcig[0]*omg[2]));
            r2g[1] = -(Rcig[2]*vig[0] + Rcig[5]*vig[1] + Rcig[8]*vig[2] + (Tcig[0]*omg[1] - Tcig[1]*omg[0]));
        }
        __syncthreads();

        // ======== PHASE 2: T9 ; GA = G @ A ========
        {
            float a = s.A[tid];
#pragma unroll
            for (int m = 0; m < 12; ++m) {
                int col = (m < 6) ? m : m + 3;
                a += s.L[t9aR12+m] * s.A[col*21 + t9aC];
            }
            s.T9[tid] = a;
            if (t9bV) {
                float b = s.A[t9b];
#pragma unroll
                for (int m = 0; m < 12; ++m) {
                    int col = (m < 6) ? m : m + 3;
                    b += s.L[t9bR12+m] * s.A[col*21 + t9bC];
                }
                s.T9[t9b] = b;
            }
        }
        if (gaV) {
            float acc = 0.f;
#pragma unroll
            for (int m = 0; m < 18; ++m) {
                int col = (m < 6) ? m : m + 3;
                acc += s.G[gaA*18+m] * s.A[col*21 + gaC];
            }
            s.GA[gaA*21+gaC] = acc;
        }
        __syncthreads();

        // ======== PHASE 3: Pn ; S ; HP ========
#pragma unroll
        for (int sl = 0; sl < 4; ++sl) if (eV[sl]) {
            int e = tid + sl*128;
            float b = eT9[sl] ? s.T9[e] : s.A[e];
            if (eJJ[sl] < 9) {
#pragma unroll
                for (int m = 0; m < 12; ++m) {
                    int col = (m < 6) ? m : m + 3;
                    float brc = eT9[sl] ? s.T9[eIIB[sl]+col] : s.A[eIIB[sl]+col];
                    b += brc * s.L[eJJ12[sl]+m];
                }
            }
            s.Pn[e] = b;
        }
        if (tid >= 61 && tid < 64) {
            int m = tid - 61;
            int a = (m == 2) ? 1 : 0;
            int bb = (m == 0) ? 0 : 1;
            float acc = 0.f;
#pragma unroll
            for (int mm = 0; mm < 18; ++mm) {
                int col = (mm < 6) ? mm : mm + 3;
                acc += s.GA[a*21+col] * s.G[bb*18+mm];
            }
            if (a == bb) acc += s.in[cur][7+a];
            s.S3[m] = acc;
        }
        if (hpV) {
            float hp = s.GA[hpA*21+hpC];
            if (hpC < 9) {
#pragma unroll
                for (int m = 0; m < 12; ++m) {
                    int col = (m < 6) ? m : m + 3;
                    hp += s.GA[hpA*21+col] * s.L[hpC*12+m];
                }
            }
            s.HP[hpA*21+hpC] = hp;
        }
        __syncthreads();

        // ======== PHASE 4: Joseph P-update ; state update ; prefetch STS ========
        {
            const float S00 = s.S3[0], S01 = s.S3[1], S11 = s.S3[2];
            const float idet = 1.f / (S00*S11 - S01*S01);
            const float Si00 = S11*idet, Si01 = -S01*idet, Si11 = S00*idet;
#pragma unroll
            for (int sl = 0; sl < 4; ++sl) if (eV[sl]) {
                int e = tid + sl*128;
                float hp0i = s.HP[eII[sl]], hp1i = s.HP[21+eII[sl]];
                float hp0j = s.HP[eJJ[sl]], hp1j = s.HP[21+eJJ[sl]];
                float Ki0 = Si00*hp0i + Si01*hp1i, Ki1 = Si01*hp0i + Si11*hp1i;
                float Kj0 = Si00*hp0j + Si01*hp1j, Kj1 = Si01*hp0j + Si11*hp1j;
                float KSi0 = Ki0*S00 + Ki1*S01, KSi1 = Ki0*S01 + Ki1*S11;
                float v = 0.5f*(s.Pn[e] + s.Pn[eJJT[sl]])
                        - (Ki0*hp0j + Ki1*hp1j) - (Kj0*hp0i + Kj1*hp1i)
                        + (KSi0*Kj0 + KSi1*Kj1);
                s.P[e] = v;
            }
        }
        if (pfV && (i + 1 < N)) s.in[nxt][tid-64] = pf;
        if (tid == 96) {
            const float S00 = s.S3[0], S01 = s.S3[1], S11 = s.S3[2];
            const float idet = 1.f / (S00*S11 - S01*S01);
            const float Si00 = S11*idet, Si01 = -S01*idet, Si11 = S00*idet;
            const float w0 = Si00*r2g[0] + Si01*r2g[1];
            const float w1 = Si01*r2g[0] + Si11*r2g[1];
            float dx[21];
#pragma unroll
            for (int c2 = 0; c2 < 21; ++c2) dx[c2] = s.HP[c2]*w0 + s.HP[21+c2]*w1;
            float a2 = dx[0]*dx[0] + dx[1]*dx[1] + dx[2]*dx[2];
            float c, sa, oc; so3c(a2, c, sa, oc);
            float j1 = j1c(a2);
            float dR[9], J[9];
#pragma unroll
            for (int p = 0; p < 3; ++p)
#pragma unroll
                for (int q = 0; q < 3; ++q) {
                    dR[p*3+q] = ((p==q)?c:0.f)  + oc*dx[p]*dx[q] + sa*skf(dx, p, q);
                    J[p*3+q]  = ((p==q)?sa:0.f) + j1*dx[p]*dx[q] + oc*skf(dx, p, q);
                }
            float x0[3], x1[3];
#pragma unroll
            for (int q = 0; q < 3; ++q) {
                x0[q] = J[q*3+0]*dx[3] + J[q*3+1]*dx[4] + J[q*3+2]*dx[5];
                x1[q] = J[q*3+0]*dx[6] + J[q*3+1]*dx[7] + J[q*3+2]*dx[8];
            }
            float Ru[9];
#pragma unroll
            for (int p = 0; p < 3; ++p)
#pragma unroll
                for (int q = 0; q < 3; ++q)
                    Ru[p*3+q] = dR[p*3+0]*rn[0*3+q] + dR[p*3+1]*rn[1*3+q] + dR[p*3+2]*rn[2*3+q];
#pragma unroll
            for (int q = 0; q < 3; ++q) {
                float vu = dR[q*3+0]*vn[0]  + dR[q*3+1]*vn[1]  + dR[q*3+2]*vn[2]  + x0[q];
                float pu = dR[q*3+0]*pn3[0] + dR[q*3+1]*pn3[1] + dR[q*3+2]*pn3[2] + x1[q];
                Vg[q] = vu; Ppg[q] = pu;
                Bomg[q] += dx[9+q]; Bacg[q] += dx[12+q]; Tcig[q] += dx[18+q];
            }
#pragma unroll
            for (int m = 0; m < 9; ++m) Rg[m] = Ru[m];
            {
                float y0 = dx[15], y1 = dx[16], y2 = dx[17];
                float b2 = y0*y0 + y1*y1 + y2*y2;
                float cc2, sa2, oc2; so3c(b2, cc2, sa2, oc2);
                float yv[3] = {y0, y1, y2};
                float E2[9];
#pragma unroll
                for (int p = 0; p < 3; ++p)
#pragma unroll
                    for (int q = 0; q < 3; ++q)
                        E2[p*3+q] = ((p==q)?cc2:0.f) + oc2*yv[p]*yv[q] + sa2*skf(yv, p, q);
                float Rc[9];
#pragma unroll
                for (int p = 0; p < 3; ++p)
#pragma unroll
                    for (int q = 0; q < 3; ++q)
                        Rc[p*3+q] = E2[p*3+0]*Rcig[0*3+q] + E2[p*3+1]*Rcig[1*3+q] + E2[p*3+2]*Rcig[2*3+q];
#pragma unroll
                for (int m = 0; m < 9; ++m) Rcig[m] = Rc[m];
            }
            if (i % 100 == 0) {
                normrot(Rg);
                if (i % 1000 == 0) normrot(Rcig);
            }
#pragma unroll
            for (int m = 0; m < 9; ++m) s.mir[m] = Rg[m];
#pragma unroll
            for (int q = 0; q < 3; ++q) {
                s.mir[9+q] = Vg[q]; s.mir[12+q] = Ppg[q]; s.mir[15+q] = Bomg[q];
                s.mir[18+q] = Bacg[q]; s.mir[30+q] = Tcig[q];
            }
#pragma unroll
            for (int m = 0; m < 9; ++m) s.mir[21+m] = Rcig[m];
        }
        __syncthreads();
    }

    // ---------- epilogue: final state row ----------
    if (tid < 33) *outPtr = s.mir[tid];
}

extern "C" void kernel_launch(void* const* d_in, const int* in_sizes, int n_in,
                              void* d_out, int out_size) {
    const float* t    = (const float*)d_in[0];
    const float* u    = (const float*)d_in[1];
    const float* mcov = (const float*)d_in[2];
    const float* vmes = (const float*)d_in[3];
    const float* ang0 = (const float*)d_in[5];
    float* out = (float*)d_out;
    int N = in_sizes[0];
    iekf_kernel<<<1, NT>>>(t, u, mcov, vmes, ang0, out, N);
}